// round 5
// baseline (speedup 1.0000x reference)
#include <cuda_runtime.h>
#include <cuda_bf16.h>
#include <cstdint>

// Problem constants
#define BB 8
#define SS 8192
#define DD 1024
#define NROWS (BB * SS)   // 65536 token rows
#define BINS 4096         // 12-bit buckets: sign + 8 exp + 3 mantissa bits
#define BSHIFT 20         // mono >> 20 -> 12-bit bucket

// Scratch (allocation-free rule: __device__ globals).
// g_hist is zero at module load; select_kernel re-zeroes its row after
// consuming it, so every call (and every graph replay) sees a clean histogram.
__device__ float        g_scores[NROWS];
__device__ unsigned int g_hist[BB * BINS];

__device__ __forceinline__ unsigned int mono_of(float s) {
    unsigned int bits = __float_as_uint(s);
    return (bits & 0x80000000u) ? ~bits : (bits | 0x80000000u);
}

// ---------------------------------------------------------------------------
// Kernel 1: scores[b,s] = dot(hidden[b,s,:], w) + bias; bucket histogram of
// active tokens accumulated via one spread-address global atomic per token.
// One warp per token row; float4 vectorized; warp tree reduction.
// ---------------------------------------------------------------------------
__global__ __launch_bounds__(256) void score_kernel(
    const float4* __restrict__ hidden,        // NROWS * 256 float4
    const unsigned int* __restrict__ active,  // NROWS 32-bit bools
    const float4* __restrict__ w4,            // 256 float4
    const float*  __restrict__ bias)
{
    int gwarp = (blockIdx.x * blockDim.x + threadIdx.x) >> 5;
    int lane  = threadIdx.x & 31;
    if (gwarp >= NROWS) return;

    const float4* row = hidden + (size_t)gwarp * (DD / 4);

    float acc = 0.f;
#pragma unroll
    for (int j = 0; j < 8; ++j) {
        float4 x = row[lane + j * 32];
        float4 w = w4[lane + j * 32];
        acc = fmaf(x.x, w.x, acc);
        acc = fmaf(x.y, w.y, acc);
        acc = fmaf(x.z, w.z, acc);
        acc = fmaf(x.w, w.w, acc);
    }

    // hoist the (L1-resident) scalar loads so their latency hides under the shfl tree
    float b_val = *bias;
    unsigned int act = active[gwarp];

#pragma unroll
    for (int o = 16; o > 0; o >>= 1)
        acc += __shfl_down_sync(0xffffffffu, acc, o);

    if (lane == 0) {
        float s = acc + b_val;
        g_scores[gwarp] = s;
        if (act != 0u) {
            int b = gwarp >> 13;  // token / SS
            atomicAdd(&g_hist[b * BINS + (mono_of(s) >> BSHIFT)], 1u);
        }
    }
}

// ---------------------------------------------------------------------------
// Kernel 2: per batch row, pick the top-k using the prebuilt bucket histogram.
//   read hist row into registers, then immediately zero it (self-resetting)
//   suffix-scan 4096 bins -> pivot bucket + residual m
//   one pass: bucket > pivot -> keep; bucket == pivot -> candidate
//   exact stable tie resolution among candidates via 64-bit (mono, ~idx) keys
// ---------------------------------------------------------------------------
__global__ __launch_bounds__(1024) void select_kernel(
    const unsigned int* __restrict__ active,  // [BB, SS]
    float* __restrict__ out)                  // [BB, SS] bool as float32
{
    __shared__ unsigned int warp_sums[32];
    __shared__ int s_n;
    __shared__ int s_pivot;
    __shared__ unsigned int s_m;
    __shared__ int s_cnt;
    __shared__ unsigned long long cand[1024];

    const int row  = blockIdx.x;
    const int tid  = threadIdx.x;
    const int lane = tid & 31;
    const int wid  = tid >> 5;

    unsigned int* hist = g_hist + row * BINS;
    const float*        sc = g_scores + (size_t)row * SS;
    const unsigned int* am = active   + (size_t)row * SS;
    float*              op = out      + (size_t)row * SS;

    if (tid == 0) s_cnt = 0;

    // Thread t covers buckets [(1023-t)*4, (1023-t)*4+3]; ascending t == descending buckets
    uint4 h = ((const uint4*)hist)[1023 - tid];
    // self-reset: each thread zeroes exactly the uint4 it just read
    ((uint4*)hist)[1023 - tid] = make_uint4(0u, 0u, 0u, 0u);
    unsigned int S = h.x + h.y + h.z + h.w;

    // block inclusive scan over thread sums (t ascending)
    unsigned int inc = S;
#pragma unroll
    for (int o = 1; o < 32; o <<= 1) {
        unsigned int v = __shfl_up_sync(0xffffffffu, inc, o);
        if (lane >= o) inc += v;
    }
    if (lane == 31) warp_sums[wid] = inc;
    __syncthreads();
    if (wid == 0) {
        unsigned int w = warp_sums[lane];
        unsigned int wi = w;
#pragma unroll
        for (int o = 1; o < 32; o <<= 1) {
            unsigned int v = __shfl_up_sync(0xffffffffu, wi, o);
            if (lane >= o) wi += v;
        }
        warp_sums[lane] = wi - w;         // exclusive warp offsets
        if (lane == 31) s_n = (int)wi;    // total active
    }
    __syncthreads();
    inc += warp_sums[wid];
    unsigned int exc = inc - S;

    const int n_active = s_n;
    if (n_active == 0) {
        for (int i = tid; i < SS; i += 1024) op[i] = 0.0f;
        return;
    }
    const unsigned int kk = (unsigned int)max(1, (n_active + 1) >> 1);

    // exactly one thread owns the pivot: exc < kk <= inc
    if (exc < kk && kk <= inc) {
        int base = (1023 - tid) * 4;
        unsigned int cum = exc;
        unsigned int v[4] = { h.w, h.z, h.y, h.x };  // descending bucket order
#pragma unroll
        for (int j = 0; j < 4; ++j) {
            if (cum + v[j] >= kk) { s_pivot = base + 3 - j; s_m = kk - cum; break; }
            cum += v[j];
        }
    }
    __syncthreads();
    const int pivot = s_pivot;
    const unsigned int m = s_m;

    // single pass: write keeps, collect pivot-bucket candidates
    for (int i = tid; i < SS; i += 1024) {
        float o = 0.0f;
        if (am[i] != 0u) {
            unsigned int mono = mono_of(sc[i]);
            int bkt = (int)(mono >> BSHIFT);
            if (bkt > pivot) {
                o = 1.0f;
            } else if (bkt == pivot) {
                int p = atomicAdd(&s_cnt, 1);
                if (p < 1024)
                    cand[p] = (((unsigned long long)mono) << 32)
                            | (unsigned long long)(0xFFFFFFFFu - (unsigned)i);
            }
        }
        op[i] = o;
    }
    __syncthreads();

    // exact stable rank among candidates (mono desc, index asc via ~idx)
    const int C = min(s_cnt, 1024);
    for (int c = tid; c < C; c += 1024) {
        unsigned long long kc = cand[c];
        unsigned int rank = 0;
        for (int j = 0; j < C; ++j)
            rank += (cand[j] > kc);
        if (rank < m) {
            unsigned int idx = 0xFFFFFFFFu - (unsigned int)(kc & 0xFFFFFFFFull);
            op[idx] = 1.0f;
        }
    }
}

// ---------------------------------------------------------------------------
extern "C" void kernel_launch(void* const* d_in, const int* in_sizes, int n_in,
                              void* d_out, int out_size)
{
    const float4*       hidden = (const float4*)d_in[0];
    const unsigned int* mask   = (const unsigned int*)d_in[1];
    const float4*       w4     = (const float4*)d_in[2];
    const float*        bias   = (const float*)d_in[3];
    float*              out    = (float*)d_out;

    score_kernel<<<NROWS / 8, 256>>>(hidden, mask, w4, bias);
    select_kernel<<<BB, 1024>>>(mask, out);
}

// round 6
// speedup vs baseline: 1.0758x; 1.0758x over previous
#include <cuda_runtime.h>
#include <cuda_bf16.h>
#include <cstdint>

// Problem constants
#define BB 8
#define SS 8192
#define DD 1024
#define NROWS (BB * SS)   // 65536 token rows
#define BINS 4096         // 12-bit buckets: sign + 8 exp + 3 mantissa bits
#define BSHIFT 20         // mono >> 20 -> 12-bit bucket
#define CAND_CAP 2048

// Scratch (allocation-free rule: __device__ globals).
// g_hist is zero at module load; pivot_kernel re-zeroes its row after
// consuming it, so every call (and every graph replay) sees a clean histogram.
__device__ float              g_scores[NROWS];
__device__ unsigned int       g_hist[BB * BINS];
__device__ unsigned long long g_thresh[BB];

__device__ __forceinline__ unsigned int mono_of(float s) {
    unsigned int bits = __float_as_uint(s);
    return (bits & 0x80000000u) ? ~bits : (bits | 0x80000000u);
}

// ---------------------------------------------------------------------------
// Kernel 1: scores[b,s] = dot(hidden[b,s,:], w) + bias; bucket histogram of
// active tokens accumulated via one spread-address global atomic per token.
// One warp per token row; float4 vectorized; warp tree reduction.
// ---------------------------------------------------------------------------
__global__ __launch_bounds__(256) void score_kernel(
    const float4* __restrict__ hidden,        // NROWS * 256 float4
    const unsigned int* __restrict__ active,  // NROWS 32-bit bools
    const float4* __restrict__ w4,            // 256 float4
    const float*  __restrict__ bias)
{
    int gwarp = (blockIdx.x * blockDim.x + threadIdx.x) >> 5;
    int lane  = threadIdx.x & 31;
    if (gwarp >= NROWS) return;

    const float4* row = hidden + (size_t)gwarp * (DD / 4);

    float acc = 0.f;
#pragma unroll
    for (int j = 0; j < 8; ++j) {
        float4 x = row[lane + j * 32];
        float4 w = w4[lane + j * 32];
        acc = fmaf(x.x, w.x, acc);
        acc = fmaf(x.y, w.y, acc);
        acc = fmaf(x.z, w.z, acc);
        acc = fmaf(x.w, w.w, acc);
    }

    float b_val = *bias;
    unsigned int act = active[gwarp];

#pragma unroll
    for (int o = 16; o > 0; o >>= 1)
        acc += __shfl_down_sync(0xffffffffu, acc, o);

    if (lane == 0) {
        float s = acc + b_val;
        g_scores[gwarp] = s;
        if (act != 0u) {
            int b = gwarp >> 13;  // token / SS
            atomicAdd(&g_hist[b * BINS + (mono_of(s) >> BSHIFT)], 1u);
        }
    }
}

// ---------------------------------------------------------------------------
// Kernel 2 (grid=8): per batch row, compute the EXACT 64-bit threshold key.
//   read hist row into registers, then zero it (self-resetting)
//   suffix-scan 4096 bins -> pivot bucket + residual m
//   one row pass collecting pivot-bucket candidate keys
//   rank candidates (unique keys) -> threshold = m-th largest candidate key
// No output writes here — that is the grid-wide kernel 3's job.
// ---------------------------------------------------------------------------
__global__ __launch_bounds__(1024) void pivot_kernel(
    const unsigned int* __restrict__ active)  // [BB, SS]
{
    __shared__ unsigned int warp_sums[32];
    __shared__ int s_n;
    __shared__ int s_pivot;
    __shared__ unsigned int s_m;
    __shared__ int s_cnt;
    __shared__ unsigned long long cand[CAND_CAP];

    const int row  = blockIdx.x;
    const int tid  = threadIdx.x;
    const int lane = tid & 31;
    const int wid  = tid >> 5;

    unsigned int* hist = g_hist + row * BINS;
    const float*        sc = g_scores + (size_t)row * SS;
    const unsigned int* am = active   + (size_t)row * SS;

    if (tid == 0) s_cnt = 0;

    // Thread t covers buckets [(1023-t)*4, (1023-t)*4+3]; ascending t == descending buckets
    uint4 h = ((const uint4*)hist)[1023 - tid];
    ((uint4*)hist)[1023 - tid] = make_uint4(0u, 0u, 0u, 0u);  // self-reset
    unsigned int S = h.x + h.y + h.z + h.w;

    // block inclusive scan over thread sums (t ascending)
    unsigned int inc = S;
#pragma unroll
    for (int o = 1; o < 32; o <<= 1) {
        unsigned int v = __shfl_up_sync(0xffffffffu, inc, o);
        if (lane >= o) inc += v;
    }
    if (lane == 31) warp_sums[wid] = inc;
    __syncthreads();
    if (wid == 0) {
        unsigned int w = warp_sums[lane];
        unsigned int wi = w;
#pragma unroll
        for (int o = 1; o < 32; o <<= 1) {
            unsigned int v = __shfl_up_sync(0xffffffffu, wi, o);
            if (lane >= o) wi += v;
        }
        warp_sums[lane] = wi - w;         // exclusive warp offsets
        if (lane == 31) s_n = (int)wi;    // total active
    }
    __syncthreads();
    inc += warp_sums[wid];
    unsigned int exc = inc - S;

    const int n_active = s_n;
    if (n_active == 0) {
        // no active tokens: no token has key >= ~0ull (keys are < 2^64-1 here,
        // and inactive tokens are masked in the output kernel anyway)
        if (tid == 0) g_thresh[row] = ~0ull;
        return;
    }
    const unsigned int kk = (unsigned int)max(1, (n_active + 1) >> 1);

    // exactly one thread owns the pivot: exc < kk <= inc
    if (exc < kk && kk <= inc) {
        int base = (1023 - tid) * 4;
        unsigned int cum = exc;
        unsigned int v[4] = { h.w, h.z, h.y, h.x };  // descending bucket order
#pragma unroll
        for (int j = 0; j < 4; ++j) {
            if (cum + v[j] >= kk) { s_pivot = base + 3 - j; s_m = kk - cum; break; }
            cum += v[j];
        }
    }
    __syncthreads();
    const int pivot = s_pivot;
    const unsigned int m = s_m;   // 1 <= m <= hist[pivot]

    // row pass: collect pivot-bucket candidate keys
    for (int i = tid; i < SS; i += 1024) {
        if (am[i] != 0u) {
            unsigned int mono = mono_of(sc[i]);
            if ((int)(mono >> BSHIFT) == pivot) {
                int p = atomicAdd(&s_cnt, 1);
                if (p < CAND_CAP)
                    cand[p] = (((unsigned long long)mono) << 32)
                            | (unsigned long long)(0xFFFFFFFFu - (unsigned)i);
            }
        }
    }
    __syncthreads();

    // threshold = m-th largest candidate key (keys unique -> exactly one match)
    const int C = min(s_cnt, CAND_CAP);
    for (int c = tid; c < C; c += 1024) {
        unsigned long long kc = cand[c];
        unsigned int rank = 0;
        for (int j = 0; j < C; ++j)
            rank += (cand[j] > kc);
        if (rank == m - 1)
            g_thresh[row] = kc;
    }
}

// ---------------------------------------------------------------------------
// Kernel 3 (grid-wide, one thread per token): out = active && key >= thresh
// ---------------------------------------------------------------------------
__global__ __launch_bounds__(1024) void output_kernel(
    const unsigned int* __restrict__ active,
    float* __restrict__ out)
{
    int i = blockIdx.x * 1024 + threadIdx.x;   // 64 blocks x 1024 = NROWS
    unsigned int act = active[i];
    float s = g_scores[i];
    unsigned long long th = __ldg(&g_thresh[i >> 13]);
    unsigned long long key = (((unsigned long long)mono_of(s)) << 32)
                           | (unsigned long long)(0xFFFFFFFFu - (unsigned)(i & (SS - 1)));
    out[i] = (act != 0u && key >= th) ? 1.0f : 0.0f;
}

// ---------------------------------------------------------------------------
extern "C" void kernel_launch(void* const* d_in, const int* in_sizes, int n_in,
                              void* d_out, int out_size)
{
    const float4*       hidden = (const float4*)d_in[0];
    const unsigned int* mask   = (const unsigned int*)d_in[1];
    const float4*       w4     = (const float4*)d_in[2];
    const float*        bias   = (const float*)d_in[3];
    float*              out    = (float*)d_out;

    score_kernel<<<NROWS / 8, 256>>>(hidden, mask, w4, bias);
    pivot_kernel<<<BB, 1024>>>(mask);
    output_kernel<<<NROWS / 1024, 1024>>>(mask, out);
}

// round 11
// speedup vs baseline: 1.1711x; 1.0886x over previous
#include <cuda_runtime.h>
#include <cuda_bf16.h>
#include <cstdint>

// Problem constants
#define BB 8
#define SS 8192
#define DD 1024
#define NROWS (BB * SS)   // 65536 token rows
#define BINS 4096         // 12-bit buckets: sign + 8 exp + 3 mantissa bits
#define BSHIFT 20         // mono >> 20 -> 12-bit bucket
#define CAND_CAP 2048

// Scratch (allocation-free rule: __device__ globals).
// g_hist is zero at module load; pivot_kernel re-zeroes its row after
// consuming it, so every call (and every graph replay) sees a clean histogram.
// g_scores entries for INACTIVE tokens are never written and never read
// (pivot reads only active entries; output masks by act), so skipping them
// is deterministic.
__device__ float              g_scores[NROWS];
__device__ unsigned int       g_hist[BB * BINS];
__device__ unsigned long long g_thresh[BB];

__device__ __forceinline__ unsigned int mono_of(float s) {
    unsigned int bits = __float_as_uint(s);
    return (bits & 0x80000000u) ? ~bits : (bits | 0x80000000u);
}

// ---------------------------------------------------------------------------
// Kernel 1: scores[b,s] = dot(hidden[b,s,:], w) + bias for ACTIVE tokens only.
// One warp per token row; inactive rows early-out (their 4 KB row is never
// read -> ~20% DRAM traffic saved). float4 vectorized; warp tree reduction;
// bucket histogram via one spread-address global atomic per active token.
// ---------------------------------------------------------------------------
__global__ __launch_bounds__(256) void score_kernel(
    const float4* __restrict__ hidden,        // NROWS * 256 float4
    const unsigned int* __restrict__ active,  // NROWS 32-bit bools
    const float4* __restrict__ w4,            // 256 float4
    const float*  __restrict__ bias)
{
    int gwarp = (blockIdx.x * blockDim.x + threadIdx.x) >> 5;
    int lane  = threadIdx.x & 31;

    // gate everything on the row's mask word (uniform across the warp)
    if (active[gwarp] == 0u) return;

    const float4* row = hidden + (size_t)gwarp * (DD / 4);

    float acc = 0.f;
#pragma unroll
    for (int j = 0; j < 8; ++j) {
        float4 x = row[lane + j * 32];
        float4 w = w4[lane + j * 32];
        acc = fmaf(x.x, w.x, acc);
        acc = fmaf(x.y, w.y, acc);
        acc = fmaf(x.z, w.z, acc);
        acc = fmaf(x.w, w.w, acc);
    }

    float b_val = *bias;   // L1-resident; latency hides under the shfl tree

#pragma unroll
    for (int o = 16; o > 0; o >>= 1)
        acc += __shfl_down_sync(0xffffffffu, acc, o);

    if (lane == 0) {
        float s = acc + b_val;
        g_scores[gwarp] = s;
        int b = gwarp >> 13;  // token / SS
        atomicAdd(&g_hist[b * BINS + (mono_of(s) >> BSHIFT)], 1u);
    }
}

// ---------------------------------------------------------------------------
// Kernel 2 (grid=8): per batch row, compute the EXACT 64-bit threshold key.
//   read hist row into registers, then zero it (self-resetting)
//   suffix-scan 4096 bins -> pivot bucket + residual m
//   one row pass collecting pivot-bucket candidate keys
//   rank candidates (unique keys) -> threshold = m-th largest candidate key
// ---------------------------------------------------------------------------
__global__ __launch_bounds__(1024) void pivot_kernel(
    const unsigned int* __restrict__ active)  // [BB, SS]
{
    __shared__ unsigned int warp_sums[32];
    __shared__ int s_n;
    __shared__ int s_pivot;
    __shared__ unsigned int s_m;
    __shared__ int s_cnt;
    __shared__ unsigned long long cand[CAND_CAP];

    const int row  = blockIdx.x;
    const int tid  = threadIdx.x;
    const int lane = tid & 31;
    const int wid  = tid >> 5;

    unsigned int* hist = g_hist + row * BINS;
    const float*        sc = g_scores + (size_t)row * SS;
    const unsigned int* am = active   + (size_t)row * SS;

    if (tid == 0) s_cnt = 0;

    // Thread t covers buckets [(1023-t)*4, (1023-t)*4+3]; ascending t == descending buckets
    uint4 h = ((const uint4*)hist)[1023 - tid];
    ((uint4*)hist)[1023 - tid] = make_uint4(0u, 0u, 0u, 0u);  // self-reset
    unsigned int S = h.x + h.y + h.z + h.w;

    // block inclusive scan over thread sums (t ascending)
    unsigned int inc = S;
#pragma unroll
    for (int o = 1; o < 32; o <<= 1) {
        unsigned int v = __shfl_up_sync(0xffffffffu, inc, o);
        if (lane >= o) inc += v;
    }
    if (lane == 31) warp_sums[wid] = inc;
    __syncthreads();
    if (wid == 0) {
        unsigned int w = warp_sums[lane];
        unsigned int wi = w;
#pragma unroll
        for (int o = 1; o < 32; o <<= 1) {
            unsigned int v = __shfl_up_sync(0xffffffffu, wi, o);
            if (lane >= o) wi += v;
        }
        warp_sums[lane] = wi - w;         // exclusive warp offsets
        if (lane == 31) s_n = (int)wi;    // total active
    }
    __syncthreads();
    inc += warp_sums[wid];
    unsigned int exc = inc - S;

    const int n_active = s_n;
    if (n_active == 0) {
        if (tid == 0) g_thresh[row] = ~0ull;  // output masks by act anyway
        return;
    }
    const unsigned int kk = (unsigned int)max(1, (n_active + 1) >> 1);

    // exactly one thread owns the pivot: exc < kk <= inc
    if (exc < kk && kk <= inc) {
        int base = (1023 - tid) * 4;
        unsigned int cum = exc;
        unsigned int v[4] = { h.w, h.z, h.y, h.x };  // descending bucket order
#pragma unroll
        for (int j = 0; j < 4; ++j) {
            if (cum + v[j] >= kk) { s_pivot = base + 3 - j; s_m = kk - cum; break; }
            cum += v[j];
        }
    }
    __syncthreads();
    const int pivot = s_pivot;
    const unsigned int m = s_m;   // 1 <= m <= hist[pivot]

    // row pass: collect pivot-bucket candidate keys (active tokens only)
    for (int i = tid; i < SS; i += 1024) {
        if (am[i] != 0u) {
            unsigned int mono = mono_of(sc[i]);
            if ((int)(mono >> BSHIFT) == pivot) {
                int p = atomicAdd(&s_cnt, 1);
                if (p < CAND_CAP)
                    cand[p] = (((unsigned long long)mono) << 32)
                            | (unsigned long long)(0xFFFFFFFFu - (unsigned)i);
            }
        }
    }
    __syncthreads();

    // threshold = m-th largest candidate key (keys unique -> exactly one match)
    const int C = min(s_cnt, CAND_CAP);
    for (int c = tid; c < C; c += 1024) {
        unsigned long long kc = cand[c];
        unsigned int rank = 0;
        for (int j = 0; j < C; ++j)
            rank += (cand[j] > kc);
        if (rank == m - 1)
            g_thresh[row] = kc;
    }
}

// ---------------------------------------------------------------------------
// Kernel 3 (grid-wide, one thread per token): out = active && key >= thresh
// (g_scores of inactive tokens may be stale/zero; the act mask hides them)
// ---------------------------------------------------------------------------
__global__ __launch_bounds__(1024) void output_kernel(
    const unsigned int* __restrict__ active,
    float* __restrict__ out)
{
    int i = blockIdx.x * 1024 + threadIdx.x;   // 64 blocks x 1024 = NROWS
    unsigned int act = active[i];
    float s = g_scores[i];
    unsigned long long th = __ldg(&g_thresh[i >> 13]);
    unsigned long long key = (((unsigned long long)mono_of(s)) << 32)
                           | (unsigned long long)(0xFFFFFFFFu - (unsigned)(i & (SS - 1)));
    out[i] = (act != 0u && key >= th) ? 1.0f : 0.0f;
}

// ---------------------------------------------------------------------------
extern "C" void kernel_launch(void* const* d_in, const int* in_sizes, int n_in,
                              void* d_out, int out_size)
{
    const float4*       hidden = (const float4*)d_in[0];
    const unsigned int* mask   = (const unsigned int*)d_in[1];
    const float4*       w4     = (const float4*)d_in[2];
    const float*        bias   = (const float*)d_in[3];
    float*              out    = (float*)d_out;

    score_kernel<<<NROWS / 8, 256>>>(hidden, mask, w4, bias);
    pivot_kernel<<<BB, 1024>>>(mask);
    output_kernel<<<NROWS / 1024, 1024>>>(mask, out);
}

// round 12
// speedup vs baseline: 1.3003x; 1.1104x over previous
#include <cuda_runtime.h>
#include <cuda_bf16.h>
#include <cstdint>

// Problem constants
#define BB 8
#define SS 8192
#define DD 1024
#define NROWS (BB * SS)   // 65536 token rows
#define BINS 4096         // 12-bit buckets: sign + 8 exp + 3 mantissa bits
#define BSHIFT 20         // mono >> 20 -> 12-bit bucket
#define CAND_CAP 2048

// Scratch (allocation-free rule: __device__ globals).
// g_hist: zero at load; pivot logic re-zeroes its row after consuming it.
// g_thresh: zero at load; doubles as the "threshold ready" flag (valid keys
//           are provably nonzero); the last finishing CTA per row resets it.
// g_done:   per-row count of finished CTAs; reset by the same last CTA.
__device__ float              g_scores[NROWS];
__device__ unsigned int       g_hist[BB * BINS];
__device__ unsigned long long g_thresh[BB];
__device__ unsigned int       g_done[BB];

__device__ __forceinline__ unsigned int mono_of(float s) {
    unsigned int bits = __float_as_uint(s);
    return (bits & 0x80000000u) ? ~bits : (bits | 0x80000000u);
}

// ---------------------------------------------------------------------------
// Kernel 1: scores for ACTIVE tokens only; TWO consecutive rows per warp to
// raise per-warp MLP (restores DRAM pressure lost to inactive-row early-outs).
// ---------------------------------------------------------------------------
__global__ __launch_bounds__(256) void score_kernel(
    const float4* __restrict__ hidden,        // NROWS * 256 float4
    const unsigned int* __restrict__ active,  // NROWS 32-bit bools
    const float4* __restrict__ w4,            // 256 float4
    const float*  __restrict__ bias)
{
    int gwarp = (blockIdx.x * blockDim.x + threadIdx.x) >> 5;  // 0..NROWS/2-1
    int lane  = threadIdx.x & 31;

    const int r0 = gwarp * 2;
    const int r1 = r0 + 1;
    const unsigned int a0 = active[r0];
    const unsigned int a1 = active[r1];
    if ((a0 | a1) == 0u) return;

    const float4* row0 = hidden + (size_t)r0 * (DD / 4);
    const float4* row1 = hidden + (size_t)r1 * (DD / 4);

    float acc0 = 0.f, acc1 = 0.f;

    if (a0 && a1) {
        // interleave both rows' loads -> ~16 outstanding LDG.128 per warp
#pragma unroll
        for (int j = 0; j < 8; ++j) {
            float4 x0 = row0[lane + j * 32];
            float4 x1 = row1[lane + j * 32];
            float4 w  = w4[lane + j * 32];
            acc0 = fmaf(x0.x, w.x, acc0); acc1 = fmaf(x1.x, w.x, acc1);
            acc0 = fmaf(x0.y, w.y, acc0); acc1 = fmaf(x1.y, w.y, acc1);
            acc0 = fmaf(x0.z, w.z, acc0); acc1 = fmaf(x1.z, w.z, acc1);
            acc0 = fmaf(x0.w, w.w, acc0); acc1 = fmaf(x1.w, w.w, acc1);
        }
    } else {
        const float4* row = a0 ? row0 : row1;
        float acc = 0.f;
#pragma unroll
        for (int j = 0; j < 8; ++j) {
            float4 x = row[lane + j * 32];
            float4 w = w4[lane + j * 32];
            acc = fmaf(x.x, w.x, acc);
            acc = fmaf(x.y, w.y, acc);
            acc = fmaf(x.z, w.z, acc);
            acc = fmaf(x.w, w.w, acc);
        }
        if (a0) acc0 = acc; else acc1 = acc;
    }

    float b_val = *bias;   // L1-resident; hides under the shfl trees

#pragma unroll
    for (int o = 16; o > 0; o >>= 1) {
        acc0 += __shfl_down_sync(0xffffffffu, acc0, o);
        acc1 += __shfl_down_sync(0xffffffffu, acc1, o);
    }

    if (lane == 0) {
        int b = r0 >> 13;  // both rows in same batch (r0 even)
        if (a0) {
            float s0 = acc0 + b_val;
            g_scores[r0] = s0;
            atomicAdd(&g_hist[b * BINS + (mono_of(s0) >> BSHIFT)], 1u);
        }
        if (a1) {
            float s1 = acc1 + b_val;
            g_scores[r1] = s1;
            atomicAdd(&g_hist[b * BINS + (mono_of(s1) >> BSHIFT)], 1u);
        }
    }
}

// ---------------------------------------------------------------------------
// Kernel 2 (grid=64, all CTAs co-resident): fused pivot + output.
//   CTA c owns tokens [c*1024, c*1024+1024), row = c>>3.
//   Leader CTAs (c&7 == 0) run the pivot logic for their row and publish the
//   exact 64-bit threshold key via atomicExch into g_thresh[row] (nonzero by
//   construction -> the value is also the ready flag).
//   The other CTAs preload their token's mask/score/key into registers, then
//   spin on g_thresh[row]; output latency hides under the leader's pivot.
//   The last of the 8 CTAs per row resets g_thresh/g_done for the next replay.
// ---------------------------------------------------------------------------
__global__ __launch_bounds__(1024) void select_fused(
    const unsigned int* __restrict__ active,  // [BB, SS]
    float* __restrict__ out)                  // [BB, SS] bool as float32
{
    __shared__ unsigned int warp_sums[32];
    __shared__ int s_n;
    __shared__ int s_pivot;
    __shared__ unsigned int s_m;
    __shared__ int s_cnt;
    __shared__ unsigned long long s_th;
    __shared__ unsigned long long cand[CAND_CAP];

    const int c    = blockIdx.x;
    const int row  = c >> 3;
    const int tid  = threadIdx.x;
    const int lane = tid & 31;
    const int wid  = tid >> 5;

    // ---- preload this CTA's token (registers held across the pivot/spin) ----
    const int i = c * 1024 + tid;               // global token index
    const unsigned int act = active[i];
    const float s_val = g_scores[i];
    const unsigned long long key =
        (((unsigned long long)mono_of(s_val)) << 32)
        | (unsigned long long)(0xFFFFFFFFu - (unsigned)(i & (SS - 1)));

    unsigned long long th;

    if ((c & 7) == 0) {
        // ================= leader: pivot for this row =================
        unsigned int* hist = g_hist + row * BINS;
        const float*        sc = g_scores + (size_t)row * SS;
        const unsigned int* am = active   + (size_t)row * SS;

        if (tid == 0) s_cnt = 0;

        // Thread t covers buckets [(1023-t)*4 .. +3]; ascending t == descending buckets
        uint4 h = ((const uint4*)hist)[1023 - tid];
        ((uint4*)hist)[1023 - tid] = make_uint4(0u, 0u, 0u, 0u);  // self-reset
        unsigned int S = h.x + h.y + h.z + h.w;

        unsigned int inc = S;
#pragma unroll
        for (int o = 1; o < 32; o <<= 1) {
            unsigned int v = __shfl_up_sync(0xffffffffu, inc, o);
            if (lane >= o) inc += v;
        }
        if (lane == 31) warp_sums[wid] = inc;
        __syncthreads();
        if (wid == 0) {
            unsigned int w = warp_sums[lane];
            unsigned int wi = w;
#pragma unroll
            for (int o = 1; o < 32; o <<= 1) {
                unsigned int v = __shfl_up_sync(0xffffffffu, wi, o);
                if (lane >= o) wi += v;
            }
            warp_sums[lane] = wi - w;
            if (lane == 31) s_n = (int)wi;
        }
        __syncthreads();
        inc += warp_sums[wid];
        unsigned int exc = inc - S;

        const int n_active = s_n;
        if (n_active == 0) {
            if (tid == 0) s_th = ~0ull;   // no token passes (output masks by act too)
        } else {
            const unsigned int kk = (unsigned int)max(1, (n_active + 1) >> 1);

            if (exc < kk && kk <= inc) {   // exactly one thread owns the pivot
                int base = (1023 - tid) * 4;
                unsigned int cum = exc;
                unsigned int v[4] = { h.w, h.z, h.y, h.x };
#pragma unroll
                for (int j = 0; j < 4; ++j) {
                    if (cum + v[j] >= kk) { s_pivot = base + 3 - j; s_m = kk - cum; break; }
                    cum += v[j];
                }
            }
            __syncthreads();
            const int pivot = s_pivot;
            const unsigned int m = s_m;

            for (int t = tid; t < SS; t += 1024) {
                if (am[t] != 0u) {
                    unsigned int mono = mono_of(sc[t]);
                    if ((int)(mono >> BSHIFT) == pivot) {
                        int p = atomicAdd(&s_cnt, 1);
                        if (p < CAND_CAP)
                            cand[p] = (((unsigned long long)mono) << 32)
                                    | (unsigned long long)(0xFFFFFFFFu - (unsigned)t);
                    }
                }
            }
            __syncthreads();

            const int C = min(s_cnt, CAND_CAP);
            for (int cc = tid; cc < C; cc += 1024) {
                unsigned long long kc = cand[cc];
                unsigned int rank = 0;
                for (int j = 0; j < C; ++j)
                    rank += (cand[j] > kc);
                if (rank == m - 1)
                    s_th = kc;          // unique winner
            }
        }
        __syncthreads();
        th = s_th;
        if (tid == 0)
            atomicExch(&g_thresh[row], th);   // publish (nonzero => ready)
    } else {
        // ================= consumer: spin for the threshold =================
        if (tid == 0) {
            unsigned long long t;
            while ((t = atomicAdd(&g_thresh[row], 0ull)) == 0ull)
                __nanosleep(64);
            s_th = t;
        }
        __syncthreads();
        th = s_th;
    }

    // ---- output for this CTA's tokens (preloaded registers) ----
    out[i] = (act != 0u && key >= th) ? 1.0f : 0.0f;

    // ---- replay-state reset: last of 8 CTAs per row clears flag+counter ----
    __threadfence();
    __syncthreads();
    if (tid == 0) {
        unsigned int old = atomicAdd(&g_done[row], 1u);
        if (old == 7u) {
            atomicExch(&g_thresh[row], 0ull);
            atomicExch(&g_done[row], 0u);
        }
    }
}

// ---------------------------------------------------------------------------
extern "C" void kernel_launch(void* const* d_in, const int* in_sizes, int n_in,
                              void* d_out, int out_size)
{
    const float4*       hidden = (const float4*)d_in[0];
    const unsigned int* mask   = (const unsigned int*)d_in[1];
    const float4*       w4     = (const float4*)d_in[2];
    const float*        bias   = (const float*)d_in[3];
    float*              out    = (float*)d_out;

    score_kernel<<<(NROWS / 2) / 8, 256>>>(hidden, mask, w4, bias);
    select_fused<<<NROWS / 1024, 1024>>>(mask, out);
}

// round 13
// speedup vs baseline: 1.3065x; 1.0047x over previous
#include <cuda_runtime.h>
#include <cuda_bf16.h>
#include <cstdint>

// Problem constants
#define BB 8
#define SS 8192
#define DD 1024
#define NROWS (BB * SS)   // 65536 token rows
#define BINS 4096         // 12-bit buckets: sign + 8 exp + 3 mantissa bits
#define BSHIFT 20         // mono >> 20 -> 12-bit bucket
#define CAND_CAP 2048

// Scratch (allocation-free rule: __device__ globals). All zero at module load;
// the protocol below leaves every word zero again at kernel end, so each
// graph replay starts from a clean state (pure dataflow, no call-count logic).
__device__ float              g_scores[NROWS];
__device__ unsigned int       g_hist[BB * BINS];
__device__ unsigned long long g_cand[BB * CAND_CAP];
__device__ unsigned int       g_pivot[BB];    // packed (flag|pivot|m); nonzero = ready
__device__ int                g_ccnt[BB];     // candidate count per row
__device__ unsigned int       g_pushed[BB];   // CTAs that finished pushing
__device__ unsigned int       g_done[BB];     // CTAs fully done (reset trigger)

__device__ __forceinline__ unsigned int mono_of(float s) {
    unsigned int bits = __float_as_uint(s);
    return (bits & 0x80000000u) ? ~bits : (bits | 0x80000000u);
}

// ---------------------------------------------------------------------------
// Kernel 1: scores for ACTIVE tokens only; TWO consecutive rows per warp to
// keep per-warp MLP high despite inactive-row early-outs. (unchanged)
// ---------------------------------------------------------------------------
__global__ __launch_bounds__(256) void score_kernel(
    const float4* __restrict__ hidden,        // NROWS * 256 float4
    const unsigned int* __restrict__ active,  // NROWS 32-bit bools
    const float4* __restrict__ w4,            // 256 float4
    const float*  __restrict__ bias)
{
    int gwarp = (blockIdx.x * blockDim.x + threadIdx.x) >> 5;  // 0..NROWS/2-1
    int lane  = threadIdx.x & 31;

    const int r0 = gwarp * 2;
    const int r1 = r0 + 1;
    const unsigned int a0 = active[r0];
    const unsigned int a1 = active[r1];
    if ((a0 | a1) == 0u) return;

    const float4* row0 = hidden + (size_t)r0 * (DD / 4);
    const float4* row1 = hidden + (size_t)r1 * (DD / 4);

    float acc0 = 0.f, acc1 = 0.f;

    if (a0 && a1) {
#pragma unroll
        for (int j = 0; j < 8; ++j) {
            float4 x0 = row0[lane + j * 32];
            float4 x1 = row1[lane + j * 32];
            float4 w  = w4[lane + j * 32];
            acc0 = fmaf(x0.x, w.x, acc0); acc1 = fmaf(x1.x, w.x, acc1);
            acc0 = fmaf(x0.y, w.y, acc0); acc1 = fmaf(x1.y, w.y, acc1);
            acc0 = fmaf(x0.z, w.z, acc0); acc1 = fmaf(x1.z, w.z, acc1);
            acc0 = fmaf(x0.w, w.w, acc0); acc1 = fmaf(x1.w, w.w, acc1);
        }
    } else {
        const float4* row = a0 ? row0 : row1;
        float acc = 0.f;
#pragma unroll
        for (int j = 0; j < 8; ++j) {
            float4 x = row[lane + j * 32];
            float4 w = w4[lane + j * 32];
            acc = fmaf(x.x, w.x, acc);
            acc = fmaf(x.y, w.y, acc);
            acc = fmaf(x.z, w.z, acc);
            acc = fmaf(x.w, w.w, acc);
        }
        if (a0) acc0 = acc; else acc1 = acc;
    }

    float b_val = *bias;

#pragma unroll
    for (int o = 16; o > 0; o >>= 1) {
        acc0 += __shfl_down_sync(0xffffffffu, acc0, o);
        acc1 += __shfl_down_sync(0xffffffffu, acc1, o);
    }

    if (lane == 0) {
        int b = r0 >> 13;
        if (a0) {
            float s0 = acc0 + b_val;
            g_scores[r0] = s0;
            atomicAdd(&g_hist[b * BINS + (mono_of(s0) >> BSHIFT)], 1u);
        }
        if (a1) {
            float s1 = acc1 + b_val;
            g_scores[r1] = s1;
            atomicAdd(&g_hist[b * BINS + (mono_of(s1) >> BSHIFT)], 1u);
        }
    }
}

// ---------------------------------------------------------------------------
// Kernel 2 (grid=64, co-resident): distributed pivot + output.
//   CTA c owns tokens [c*1024, (c+1)*1024), row = c>>3; tokens preloaded
//   into registers up front.
//   Leader (c&7==0): hist read+zero, suffix scan -> (pivot, m); publishes one
//     packed nonzero word (bit31 | pivot<<14 | m).
//   ALL 8 CTAs: spin for the word, filter their OWN register-resident tokens
//     for the pivot bucket, push candidates to the global per-row buffer,
//     arrive on g_pushed; once all 8 pushed, rank own pivot-bucket tokens
//     against the C candidates (keys unique) and write outputs.
//   Last of 8 CTAs resets all per-row protocol words for the next replay.
// ---------------------------------------------------------------------------
__global__ __launch_bounds__(1024) void select_fused(
    const unsigned int* __restrict__ active,  // [BB, SS]
    float* __restrict__ out)                  // [BB, SS] bool as float32
{
    __shared__ unsigned int warp_sums[32];
    __shared__ int s_n;
    __shared__ int s_pivot;
    __shared__ unsigned int s_m;
    __shared__ unsigned int s_pk;
    __shared__ int s_C;

    const int c    = blockIdx.x;
    const int row  = c >> 3;
    const int tid  = threadIdx.x;
    const int lane = tid & 31;
    const int wid  = tid >> 5;

    // ---- preload this CTA's token into registers ----
    const int i = c * 1024 + tid;               // global token index
    const unsigned int act = active[i];
    const float s_val = g_scores[i];
    const unsigned int mono = mono_of(s_val);
    const unsigned long long key =
        (((unsigned long long)mono) << 32)
        | (unsigned long long)(0xFFFFFFFFu - (unsigned)(i & (SS - 1)));

    if ((c & 7) == 0) {
        // ============ leader: histogram scan -> (pivot, m) ============
        unsigned int* hist = g_hist + row * BINS;

        uint4 h = ((const uint4*)hist)[1023 - tid];
        ((uint4*)hist)[1023 - tid] = make_uint4(0u, 0u, 0u, 0u);  // self-reset
        unsigned int S = h.x + h.y + h.z + h.w;

        unsigned int inc = S;
#pragma unroll
        for (int o = 1; o < 32; o <<= 1) {
            unsigned int v = __shfl_up_sync(0xffffffffu, inc, o);
            if (lane >= o) inc += v;
        }
        if (lane == 31) warp_sums[wid] = inc;
        __syncthreads();
        if (wid == 0) {
            unsigned int w = warp_sums[lane];
            unsigned int wi = w;
#pragma unroll
            for (int o = 1; o < 32; o <<= 1) {
                unsigned int v = __shfl_up_sync(0xffffffffu, wi, o);
                if (lane >= o) wi += v;
            }
            warp_sums[lane] = wi - w;
            if (lane == 31) s_n = (int)wi;
        }
        if (tid == 0) { s_pivot = 0; s_m = 0u; }   // defaults (n_active == 0)
        __syncthreads();
        inc += warp_sums[wid];
        unsigned int exc = inc - S;

        const int n_active = s_n;
        if (n_active > 0) {
            const unsigned int kk = (unsigned int)max(1, (n_active + 1) >> 1);
            if (exc < kk && kk <= inc) {   // exactly one thread owns the pivot
                int base = (1023 - tid) * 4;
                unsigned int cum = exc;
                unsigned int v[4] = { h.w, h.z, h.y, h.x };
#pragma unroll
                for (int j = 0; j < 4; ++j) {
                    if (cum + v[j] >= kk) { s_pivot = base + 3 - j; s_m = kk - cum; break; }
                    cum += v[j];
                }
            }
        }
        __syncthreads();
        if (tid == 0) {
            // packed: bit31 flag | pivot (12b) << 14 | m (14b). Always nonzero.
            unsigned int pk = 0x80000000u | ((unsigned int)s_pivot << 14) | s_m;
            atomicExch(&g_pivot[row], pk);
            s_pk = pk;
        }
        __syncthreads();
    } else {
        // ============ consumers: spin for the packed pivot word ============
        if (tid == 0) {
            unsigned int t;
            while ((t = atomicAdd(&g_pivot[row], 0u)) == 0u)
                __nanosleep(32);
            s_pk = t;
        }
        __syncthreads();
    }

    const unsigned int pk    = s_pk;
    const int          pivot = (int)((pk >> 14) & 0xFFFu);
    const unsigned int m     = pk & 0x3FFFu;
    const int          bkt   = (int)(mono >> BSHIFT);

    // ---- push own pivot-bucket candidates (register-resident filter) ----
    if (act != 0u && bkt == pivot) {
        int p = atomicAdd(&g_ccnt[row], 1);
        if (p < CAND_CAP)
            g_cand[row * CAND_CAP + p] = key;
    }
    __threadfence();
    __syncthreads();
    if (tid == 0) {
        atomicAdd(&g_pushed[row], 1u);
        unsigned int t;
        while ((t = atomicAdd(&g_pushed[row], 0u)) < 8u)
            __nanosleep(32);
        s_C = atomicAdd(&g_ccnt[row], 0);
    }
    __syncthreads();
    const int C = min(s_C, CAND_CAP);

    // ---- decide + write own token ----
    float o = 0.0f;
    if (act != 0u) {
        if (bkt > pivot) {
            o = 1.0f;
        } else if (bkt == pivot) {
            const unsigned long long* cb = g_cand + row * CAND_CAP;
            unsigned int rank = 0;
            for (int j = 0; j < C; ++j)
                rank += (__ldcg(&cb[j]) > key);
            if (rank < m) o = 1.0f;
        }
    }
    out[i] = o;

    // ---- replay-state reset: last of 8 CTAs clears all protocol words ----
    __threadfence();
    __syncthreads();
    if (tid == 0) {
        unsigned int old = atomicAdd(&g_done[row], 1u);
        if (old == 7u) {
            atomicExch(&g_pivot[row], 0u);
            atomicExch((unsigned int*)&g_ccnt[row], 0u);
            atomicExch(&g_pushed[row], 0u);
            atomicExch(&g_done[row], 0u);
        }
    }
}

// ---------------------------------------------------------------------------
extern "C" void kernel_launch(void* const* d_in, const int* in_sizes, int n_in,
                              void* d_out, int out_size)
{
    const float4*       hidden = (const float4*)d_in[0];
    const unsigned int* mask   = (const unsigned int*)d_in[1];
    const float4*       w4     = (const float4*)d_in[2];
    const float*        bias   = (const float*)d_in[3];
    float*              out    = (float*)d_out;

    score_kernel<<<(NROWS / 2) / 8, 256>>>(hidden, mask, w4, bias);
    select_fused<<<NROWS / 1024, 1024>>>(mask, out);
}

// round 14
// speedup vs baseline: 1.3073x; 1.0007x over previous
#include <cuda_runtime.h>
#include <cuda_bf16.h>
#include <cstdint>

// Problem constants
#define BB 8
#define SS 8192
#define DD 1024
#define NROWS (BB * SS)   // 65536 token rows
#define BINS 4096         // 12-bit buckets: sign + 8 exp + 3 mantissa bits
#define BSHIFT 20         // mono >> 20 -> 12-bit bucket
#define CAND_CAP 2048

// Scratch (allocation-free rule: __device__ globals). All zero at module load;
// the protocol leaves every word zero at kernel end -> clean graph replays.
// Each protocol flag lives on its own 128-byte line (no false sharing; polls
// are volatile LOADS, so the L2 atomic ALU only sees the publishes).
struct PadFlag { unsigned int v; unsigned int _pad[31]; };

__device__ float              g_scores[NROWS];
__device__ unsigned int       g_hist[BB * BINS];
__device__ unsigned long long g_cand[BB * CAND_CAP];
__device__ PadFlag            g_pivot[BB];    // packed (flag|pivot|m); nonzero = ready
__device__ PadFlag            g_ccnt[BB];     // candidate count per row
__device__ PadFlag            g_pushed[BB];   // CTAs that finished pushing
__device__ PadFlag            g_done[BB];     // CTAs fully done (reset trigger)

__device__ __forceinline__ unsigned int mono_of(float s) {
    unsigned int bits = __float_as_uint(s);
    return (bits & 0x80000000u) ? ~bits : (bits | 0x80000000u);
}

// ---------------------------------------------------------------------------
// Kernel 1: scores for ACTIVE tokens only; TWO consecutive rows per warp to
// keep per-warp MLP high despite inactive-row early-outs. (unchanged)
// ---------------------------------------------------------------------------
__global__ __launch_bounds__(256) void score_kernel(
    const float4* __restrict__ hidden,        // NROWS * 256 float4
    const unsigned int* __restrict__ active,  // NROWS 32-bit bools
    const float4* __restrict__ w4,            // 256 float4
    const float*  __restrict__ bias)
{
    int gwarp = (blockIdx.x * blockDim.x + threadIdx.x) >> 5;  // 0..NROWS/2-1
    int lane  = threadIdx.x & 31;

    const int r0 = gwarp * 2;
    const int r1 = r0 + 1;
    const unsigned int a0 = active[r0];
    const unsigned int a1 = active[r1];
    if ((a0 | a1) == 0u) return;

    const float4* row0 = hidden + (size_t)r0 * (DD / 4);
    const float4* row1 = hidden + (size_t)r1 * (DD / 4);

    float acc0 = 0.f, acc1 = 0.f;

    if (a0 && a1) {
#pragma unroll
        for (int j = 0; j < 8; ++j) {
            float4 x0 = row0[lane + j * 32];
            float4 x1 = row1[lane + j * 32];
            float4 w  = w4[lane + j * 32];
            acc0 = fmaf(x0.x, w.x, acc0); acc1 = fmaf(x1.x, w.x, acc1);
            acc0 = fmaf(x0.y, w.y, acc0); acc1 = fmaf(x1.y, w.y, acc1);
            acc0 = fmaf(x0.z, w.z, acc0); acc1 = fmaf(x1.z, w.z, acc1);
            acc0 = fmaf(x0.w, w.w, acc0); acc1 = fmaf(x1.w, w.w, acc1);
        }
    } else {
        const float4* row = a0 ? row0 : row1;
        float acc = 0.f;
#pragma unroll
        for (int j = 0; j < 8; ++j) {
            float4 x = row[lane + j * 32];
            float4 w = w4[lane + j * 32];
            acc = fmaf(x.x, w.x, acc);
            acc = fmaf(x.y, w.y, acc);
            acc = fmaf(x.z, w.z, acc);
            acc = fmaf(x.w, w.w, acc);
        }
        if (a0) acc0 = acc; else acc1 = acc;
    }

    float b_val = *bias;

#pragma unroll
    for (int o = 16; o > 0; o >>= 1) {
        acc0 += __shfl_down_sync(0xffffffffu, acc0, o);
        acc1 += __shfl_down_sync(0xffffffffu, acc1, o);
    }

    if (lane == 0) {
        int b = r0 >> 13;
        if (a0) {
            float s0 = acc0 + b_val;
            g_scores[r0] = s0;
            atomicAdd(&g_hist[b * BINS + (mono_of(s0) >> BSHIFT)], 1u);
        }
        if (a1) {
            float s1 = acc1 + b_val;
            g_scores[r1] = s1;
            atomicAdd(&g_hist[b * BINS + (mono_of(s1) >> BSHIFT)], 1u);
        }
    }
}

// ---------------------------------------------------------------------------
// Kernel 2 (grid=64, co-resident): distributed pivot + output.
//   Leader (c&7==0): hist read+zero -> (pivot, m); atomicExch-publish one
//     packed nonzero word. Consumers poll with VOLATILE loads (no atomic ALU
//     pressure, own 128B line) + nanosleep backoff.
//   All CTAs: filter register-resident tokens for the pivot bucket, push
//     candidates; non-pivot tokens write their output IMMEDIATELY (no second
//     barrier on their path). Pivot-bucket outputs wait for all 8 pushes,
//     stage the C candidates in SMEM cooperatively, rank, write.
//   Last of 8 CTAs resets all per-row protocol words (clean replay state).
// ---------------------------------------------------------------------------
__global__ __launch_bounds__(1024) void select_fused(
    const unsigned int* __restrict__ active,  // [BB, SS]
    float* __restrict__ out)                  // [BB, SS] bool as float32
{
    __shared__ unsigned int warp_sums[32];
    __shared__ int s_n;
    __shared__ int s_pivot;
    __shared__ unsigned int s_m;
    __shared__ unsigned int s_pk;
    __shared__ int s_C;
    __shared__ unsigned long long s_cand[CAND_CAP];

    const int c    = blockIdx.x;
    const int row  = c >> 3;
    const int tid  = threadIdx.x;
    const int lane = tid & 31;
    const int wid  = tid >> 5;

    // ---- preload this CTA's token into registers ----
    const int i = c * 1024 + tid;               // global token index
    const unsigned int act = active[i];
    const float s_val = g_scores[i];
    const unsigned int mono = mono_of(s_val);
    const unsigned long long key =
        (((unsigned long long)mono) << 32)
        | (unsigned long long)(0xFFFFFFFFu - (unsigned)(i & (SS - 1)));

    if ((c & 7) == 0) {
        // ============ leader: histogram scan -> (pivot, m) ============
        unsigned int* hist = g_hist + row * BINS;

        uint4 h = ((const uint4*)hist)[1023 - tid];
        ((uint4*)hist)[1023 - tid] = make_uint4(0u, 0u, 0u, 0u);  // self-reset
        unsigned int S = h.x + h.y + h.z + h.w;

        unsigned int inc = S;
#pragma unroll
        for (int o = 1; o < 32; o <<= 1) {
            unsigned int v = __shfl_up_sync(0xffffffffu, inc, o);
            if (lane >= o) inc += v;
        }
        if (lane == 31) warp_sums[wid] = inc;
        __syncthreads();
        if (wid == 0) {
            unsigned int w = warp_sums[lane];
            unsigned int wi = w;
#pragma unroll
            for (int o = 1; o < 32; o <<= 1) {
                unsigned int v = __shfl_up_sync(0xffffffffu, wi, o);
                if (lane >= o) wi += v;
            }
            warp_sums[lane] = wi - w;
            if (lane == 31) s_n = (int)wi;
        }
        if (tid == 0) { s_pivot = 0; s_m = 0u; }   // defaults (n_active == 0)
        __syncthreads();
        inc += warp_sums[wid];
        unsigned int exc = inc - S;

        const int n_active = s_n;
        if (n_active > 0) {
            const unsigned int kk = (unsigned int)max(1, (n_active + 1) >> 1);
            if (exc < kk && kk <= inc) {   // exactly one thread owns the pivot
                int base = (1023 - tid) * 4;
                unsigned int cum = exc;
                unsigned int v[4] = { h.w, h.z, h.y, h.x };
#pragma unroll
                for (int j = 0; j < 4; ++j) {
                    if (cum + v[j] >= kk) { s_pivot = base + 3 - j; s_m = kk - cum; break; }
                    cum += v[j];
                }
            }
        }
        __syncthreads();
        if (tid == 0) {
            // packed: bit31 flag | pivot (12b) << 14 | m (14b). Always nonzero.
            unsigned int pk = 0x80000000u | ((unsigned int)s_pivot << 14) | s_m;
            atomicExch(&g_pivot[row].v, pk);
            s_pk = pk;
        }
        __syncthreads();
    } else {
        // ============ consumers: volatile-poll the packed pivot word ========
        if (tid == 0) {
            volatile unsigned int* p = &g_pivot[row].v;
            unsigned int t;
            while ((t = *p) == 0u)
                __nanosleep(128);
            s_pk = t;
        }
        __syncthreads();
    }

    const unsigned int pk    = s_pk;
    const int          pivot = (int)((pk >> 14) & 0xFFFu);
    const unsigned int m     = pk & 0x3FFFu;
    const int          bkt   = (int)(mono >> BSHIFT);
    const bool is_cand = (act != 0u && bkt == pivot);

    // ---- push own pivot-bucket candidates; fence only by pushing threads ----
    if (is_cand) {
        int p = atomicAdd((int*)&g_ccnt[row].v, 1);
        if (p < CAND_CAP)
            g_cand[row * CAND_CAP + p] = key;
        __threadfence();
    }

    // ---- non-pivot tokens are fully decided: write output NOW ----
    if (!is_cand)
        out[i] = (act != 0u && bkt > pivot) ? 1.0f : 0.0f;

    __syncthreads();               // pushes done CTA-wide (fences executed)
    if (tid == 0) {
        atomicAdd(&g_pushed[row].v, 1u);
        volatile unsigned int* p = &g_pushed[row].v;
        while (*p < 8u)
            __nanosleep(128);
        s_C = (int)*(volatile unsigned int*)&g_ccnt[row].v;
    }
    __syncthreads();
    const int C = min(s_C, CAND_CAP);

    // ---- stage candidates in SMEM once per CTA (parallel L2 loads) ----
    for (int j = tid; j < C; j += 1024)
        s_cand[j] = __ldcg(&g_cand[row * CAND_CAP + j]);
    __syncthreads();

    // ---- rank own pivot-bucket token against SMEM candidates ----
    if (is_cand) {
        unsigned int rank = 0;
        for (int j = 0; j < C; ++j)
            rank += (s_cand[j] > key);
        out[i] = (rank < m) ? 1.0f : 0.0f;
    }

    // ---- replay-state reset: last of 8 CTAs clears all protocol words ----
    __threadfence();
    __syncthreads();
    if (tid == 0) {
        unsigned int old = atomicAdd(&g_done[row].v, 1u);
        if (old == 7u) {
            atomicExch(&g_pivot[row].v, 0u);
            atomicExch(&g_ccnt[row].v, 0u);
            atomicExch(&g_pushed[row].v, 0u);
            atomicExch(&g_done[row].v, 0u);
        }
    }
}

// ---------------------------------------------------------------------------
extern "C" void kernel_launch(void* const* d_in, const int* in_sizes, int n_in,
                              void* d_out, int out_size)
{
    const float4*       hidden = (const float4*)d_in[0];
    const unsigned int* mask   = (const unsigned int*)d_in[1];
    const float4*       w4     = (const float4*)d_in[2];
    const float*        bias   = (const float*)d_in[3];
    float*              out    = (float*)d_out;

    score_kernel<<<(NROWS / 2) / 8, 256>>>(hidden, mask, w4, bias);
    select_fused<<<NROWS / 1024, 1024>>>(mask, out);
}